// round 14
// baseline (speedup 1.0000x reference)
#include <cuda_runtime.h>
#include <cstdint>

#define B_  16
#define J_  1024
#define L_  4096
#define D_  512
#define D4_ 128   // D/4
#define C_  64    // chunks over J
#define CH_ 16    // J_/C_

// Scratch (device globals: allocation-free per harness rules)
__device__ float g_smoothed[B_ * J_ * D_];      // 32 MiB  (chunk-local EMA)
__device__ float g_carry   [B_ * C_ * D_];      // 2 MiB   (true carry into each chunk)
__device__ int   g_idx     [B_ * L_];
__device__ float g_aprefix [B_ * J_];           // within-chunk inclusive prod of aw

// ---------------------------------------------------------------------------
// Kernel 1: chunk-local EMA with inline coefficient computation.
// grid = (C_, B_), block = 128 (d4 lanes). Threads 0..CH_-1 of warp 0 also
// compute the chunk's aprefix (inclusive product of aw, 16-lane shfl scan).
// ---------------------------------------------------------------------------
__global__ void ema_local_kernel(const float* __restrict__ emb,
                                 const float* __restrict__ conf,
                                 const int*   __restrict__ umask)
{
    const int c  = blockIdx.x;           // chunk
    const int b  = blockIdx.y;
    const int d4 = threadIdx.x;          // 0..127
    const int j0 = c * CH_;

    __shared__ float s_pw[CH_], s_aw[CH_];

    if (threadIdx.x < CH_) {             // lanes 0..15 of warp 0
        const int j = j0 + threadIdx.x;
        float p = __ldg(conf + b * J_ + j);
        p = fminf(fmaxf(p, 1e-4f), 1.0f - 1e-4f);
        const bool m = (__ldg(umask + b * J_ + j) != 0);
        const float pw = m ? p : 0.0f;
        const float aw = m ? (1.0f - p) : 1.0f;
        s_pw[threadIdx.x] = pw;
        s_aw[threadIdx.x] = aw;

        // inclusive product scan across the 16 lanes (== chunk)
        float ap = aw;
        #pragma unroll
        for (int o = 1; o < CH_; o <<= 1) {
            float n = __shfl_up_sync(0x0000ffffu, ap, o);
            if (threadIdx.x >= o) ap *= n;
        }
        g_aprefix[b * J_ + j] = ap;
    }
    __syncthreads();

    const float4* __restrict__ src =
        reinterpret_cast<const float4*>(emb) + ((size_t)(b * J_ + j0)) * D4_ + d4;
    float4* __restrict__ dst =
        reinterpret_cast<float4*>(g_smoothed) + ((size_t)(b * J_ + j0)) * D4_ + d4;

    float4 prev = make_float4(0.f, 0.f, 0.f, 0.f);

    #pragma unroll
    for (int j = 0; j < CH_; ++j) {
        const float4 cur = __ldcs(src + (size_t)j * D4_);   // read-once: stream past L2
        const float p = s_pw[j];
        const float a = s_aw[j];
        prev.x = fmaf(p, cur.x, a * prev.x);
        prev.y = fmaf(p, cur.y, a * prev.y);
        prev.z = fmaf(p, cur.z, a * prev.z);
        prev.w = fmaf(p, cur.w, a * prev.w);
        dst[(size_t)j * D4_] = prev;
    }
}

// ---------------------------------------------------------------------------
// Kernel 2: combined (independent slices):
//   grid.y == 0 : carry scan across chunks (128 active threads / batch)
//       true_end(c) = local_end(c) + A(c) * true_end(c-1)
//       carry[b,c,:] = true_end(c-1); carry[b,0,:] = 0
//   grid.y == 1 : boundary cumsum -> gather index (1024-thread block scan)
// grid = (B_, 2), block = 1024. bmask arrives as int32 (0/1).
// ---------------------------------------------------------------------------
__global__ void mid_kernel(const int* __restrict__ bmask)
{
    const int b = blockIdx.x;

    if (blockIdx.y == 0) {
        if (threadIdx.x >= D4_) return;
        const int d4 = threadIdx.x;

        const float4* __restrict__ sm = reinterpret_cast<const float4*>(g_smoothed);
        float4* __restrict__ carry    = reinterpret_cast<float4*>(g_carry);

        float4 t_end = __ldg(sm + ((size_t)(b * J_ + CH_ - 1)) * D4_ + d4);
        carry[((size_t)(b * C_)) * D4_ + d4] = make_float4(0.f, 0.f, 0.f, 0.f);

        #pragma unroll 8
        for (int c = 1; c < C_; ++c) {
            carry[((size_t)(b * C_ + c)) * D4_ + d4] = t_end;
            const int je = c * CH_ + CH_ - 1;
            const float  A  = __ldg(g_aprefix + b * J_ + je);
            const float4 le = __ldg(sm + ((size_t)(b * J_ + je)) * D4_ + d4);
            t_end.x = fmaf(A, t_end.x, le.x);
            t_end.y = fmaf(A, t_end.y, le.y);
            t_end.z = fmaf(A, t_end.z, le.z);
            t_end.w = fmaf(A, t_end.w, le.w);
        }
        return;
    }

    // ---- boundary scan: 4096 int32 bools, 4 per thread ----
    const int t = threadIdx.x;
    const int lane = t & 31, warp = t >> 5;

    const int4 v = reinterpret_cast<const int4*>(bmask + (size_t)b * L_)[t];
    const int s0 = v.x ? 1 : 0, s1 = v.y ? 1 : 0, s2 = v.z ? 1 : 0, s3 = v.w ? 1 : 0;
    const int local = s0 + s1 + s2 + s3;

    int incl = local;
    #pragma unroll
    for (int o = 1; o < 32; o <<= 1) {
        int n = __shfl_up_sync(0xffffffffu, incl, o);
        if (lane >= o) incl += n;
    }
    __shared__ int wsum[32];
    if (lane == 31) wsum[warp] = incl;
    __syncthreads();
    if (warp == 0) {
        int ws = wsum[lane];
        #pragma unroll
        for (int o = 1; o < 32; o <<= 1) {
            int n = __shfl_up_sync(0xffffffffu, ws, o);
            if (lane >= o) ws += n;
        }
        wsum[lane] = ws;  // inclusive warp prefix
    }
    __syncthreads();

    int c = incl - local + (warp > 0 ? wsum[warp - 1] : 0);  // exclusive prefix
    int4 o4;
    c += s0; o4.x = min(max(c - 1, 0), J_ - 1);
    c += s1; o4.y = min(max(c - 1, 0), J_ - 1);
    c += s2; o4.z = min(max(c - 1, 0), J_ - 1);
    c += s3; o4.w = min(max(c - 1, 0), J_ - 1);
    reinterpret_cast<int4*>(g_idx + (size_t)b * L_)[t] = o4;
}

// ---------------------------------------------------------------------------
// Kernel 3: gather + carry fixup, warp-per-row (64 B per thread).
//   out[b,l,:] = local[b,j,:] + Aprefix[b,j] * carry[b, j/CH_, :],  j = idx[b,l]
// Lane covers d4 = lane + 32k, k=0..3 -> one warp moves one 2KB row.
// grid = B_*L_/8 = 8192, block = 256 (8 warps).
// ---------------------------------------------------------------------------
__global__ void gather_kernel(float4* __restrict__ out)
{
    const int w    = (blockIdx.x * 256 + threadIdx.x) >> 5;  // global warp = b*L_+l
    const int lane = threadIdx.x & 31;
    const int b    = w >> 12;                                 // / L_

    const int   j  = __ldg(g_idx + w);
    const float ap = __ldg(g_aprefix + b * J_ + j);

    const float4* __restrict__ lo =
        reinterpret_cast<const float4*>(g_smoothed) + ((size_t)(b * J_ + j)) * D4_ + lane;
    const float4* __restrict__ cr =
        reinterpret_cast<const float4*>(g_carry) + ((size_t)(b * C_ + (j >> 4))) * D4_ + lane;
    float4* __restrict__ o = out + (size_t)w * D4_ + lane;

    #pragma unroll
    for (int k = 0; k < 4; ++k) {
        const float4 l4 = __ldg(lo + k * 32);
        const float4 c4 = __ldg(cr + k * 32);
        float4 r;
        r.x = fmaf(ap, c4.x, l4.x);
        r.y = fmaf(ap, c4.y, l4.y);
        r.z = fmaf(ap, c4.z, l4.z);
        r.w = fmaf(ap, c4.w, l4.w);
        __stcs(o + k * 32, r);
    }
}

// ---------------------------------------------------------------------------
extern "C" void kernel_launch(void* const* d_in, const int* in_sizes, int n_in,
                              void* d_out, int out_size)
{
    const float* emb   = (const float*)d_in[0];   // (B,J,D) f32
    const float* conf  = (const float*)d_in[1];   // (B,J)   f32
    const int*   umask = (const int*)d_in[2];     // (B,J)   bool->int32
    const int*   bmask = (const int*)d_in[3];     // (B,L)   bool->int32
    float4* out = (float4*)d_out;                 // (B,L,D) f32

    (void)in_sizes; (void)n_in; (void)out_size;

    ema_local_kernel<<<dim3(C_, B_), D4_>>>(emb, conf, umask);
    mid_kernel<<<dim3(B_, 2), 1024>>>(bmask);
    gather_kernel<<<(B_ * L_) / 8, 256>>>(out);
}

// round 15
// speedup vs baseline: 1.0892x; 1.0892x over previous
#include <cuda_runtime.h>
#include <cstdint>

#define B_  16
#define J_  1024
#define L_  4096
#define D_  512
#define D4_ 128   // D/4
#define C_  64    // chunks over J
#define CH_ 16    // J_/C_
#define BATCH_ 8  // explicit load batch depth (MLP per warp)

// Scratch (device globals: allocation-free per harness rules)
__device__ float g_smoothed[B_ * J_ * D_];      // 32 MiB  (chunk-local EMA)
__device__ float g_carry   [B_ * C_ * D_];      // 2 MiB   (true carry into each chunk)
__device__ int   g_idx     [B_ * L_];
__device__ float g_aprefix [B_ * J_];           // within-chunk inclusive prod of aw

// ---------------------------------------------------------------------------
// Kernel 1: chunk-local EMA with inline coefficients + fused boundary scan.
// grid = (C_+1, B_), block = 128.
//   blockIdx.x <  C_ : chunk-local EMA for (b, chunk). Explicit 8-deep load
//                      batching forces MLP=8 per warp (ptxas won't do it
//                      itself: dst may alias src in its model).
//   blockIdx.x == C_ : boundary cumsum -> gather index for batch b
//                      (128 threads x 32 contiguous elems each).
// ---------------------------------------------------------------------------
__global__ void ema_local_kernel(const float* __restrict__ emb,
                                 const float* __restrict__ conf,
                                 const int*   __restrict__ umask,
                                 const int*   __restrict__ bmask)
{
    const int b = blockIdx.y;

    __shared__ float s_pw[CH_], s_aw[CH_];
    __shared__ int   wsum[4];

    if (blockIdx.x == C_) {
        // ---- boundary scan: 4096 int32 bools, 32 contiguous per thread ----
        const int t = threadIdx.x;            // 0..127
        const int lane = t & 31, warp = t >> 5;

        int4 v[8];
        const int4* __restrict__ src4 =
            reinterpret_cast<const int4*>(bmask + (size_t)b * L_) + t * 8;
        #pragma unroll
        for (int k = 0; k < 8; ++k) v[k] = __ldg(src4 + k);

        int local = 0;
        #pragma unroll
        for (int k = 0; k < 8; ++k)
            local += (v[k].x ? 1 : 0) + (v[k].y ? 1 : 0) +
                     (v[k].z ? 1 : 0) + (v[k].w ? 1 : 0);

        int incl = local;
        #pragma unroll
        for (int o = 1; o < 32; o <<= 1) {
            int n = __shfl_up_sync(0xffffffffu, incl, o);
            if (lane >= o) incl += n;
        }
        if (lane == 31) wsum[warp] = incl;
        __syncthreads();
        if (warp == 0 && lane < 4) {
            int ws = wsum[lane];
            #pragma unroll
            for (int o = 1; o < 4; o <<= 1) {
                int n = __shfl_up_sync(0x0000000fu, ws, o);
                if (lane >= o) ws += n;
            }
            wsum[lane] = ws;  // inclusive warp prefix
        }
        __syncthreads();

        int c = incl - local + (warp > 0 ? wsum[warp - 1] : 0);  // exclusive prefix
        int4* __restrict__ dst4 =
            reinterpret_cast<int4*>(g_idx + (size_t)b * L_) + t * 8;
        #pragma unroll
        for (int k = 0; k < 8; ++k) {
            int4 o4;
            c += (v[k].x ? 1 : 0); o4.x = min(max(c - 1, 0), J_ - 1);
            c += (v[k].y ? 1 : 0); o4.y = min(max(c - 1, 0), J_ - 1);
            c += (v[k].z ? 1 : 0); o4.z = min(max(c - 1, 0), J_ - 1);
            c += (v[k].w ? 1 : 0); o4.w = min(max(c - 1, 0), J_ - 1);
            dst4[k] = o4;
        }
        return;
    }

    // ---- chunk-local EMA ----
    const int c  = blockIdx.x;           // chunk
    const int d4 = threadIdx.x;          // 0..127
    const int j0 = c * CH_;

    if (threadIdx.x < CH_) {             // lanes 0..15 of warp 0
        const int j = j0 + threadIdx.x;
        float p = __ldg(conf + b * J_ + j);
        p = fminf(fmaxf(p, 1e-4f), 1.0f - 1e-4f);
        const bool m = (__ldg(umask + b * J_ + j) != 0);
        s_pw[threadIdx.x] = m ? p : 0.0f;
        const float aw   = m ? (1.0f - p) : 1.0f;
        s_aw[threadIdx.x] = aw;

        // inclusive product scan across the 16 lanes (== chunk)
        float ap = aw;
        #pragma unroll
        for (int o = 1; o < CH_; o <<= 1) {
            float n = __shfl_up_sync(0x0000ffffu, ap, o);
            if (threadIdx.x >= o) ap *= n;
        }
        g_aprefix[b * J_ + j] = ap;
    }
    __syncthreads();

    const float4* __restrict__ src =
        reinterpret_cast<const float4*>(emb) + ((size_t)(b * J_ + j0)) * D4_ + d4;
    float4* __restrict__ dst =
        reinterpret_cast<float4*>(g_smoothed) + ((size_t)(b * J_ + j0)) * D4_ + d4;

    float4 prev = make_float4(0.f, 0.f, 0.f, 0.f);

    #pragma unroll
    for (int base = 0; base < CH_; base += BATCH_) {
        float4 v[BATCH_];
        #pragma unroll
        for (int k = 0; k < BATCH_; ++k)
            v[k] = __ldcs(src + (size_t)(base + k) * D4_);   // 8 outstanding LDGs
        #pragma unroll
        for (int k = 0; k < BATCH_; ++k) {
            const float p = s_pw[base + k];
            const float a = s_aw[base + k];
            prev.x = fmaf(p, v[k].x, a * prev.x);
            prev.y = fmaf(p, v[k].y, a * prev.y);
            prev.z = fmaf(p, v[k].z, a * prev.z);
            prev.w = fmaf(p, v[k].w, a * prev.w);
            dst[(size_t)(base + k) * D4_] = prev;
        }
    }
}

// ---------------------------------------------------------------------------
// Kernel 2: carry scan across chunks. grid = B_, block = 128 (d4).
//   true_end(c) = local_end(c) + A(c) * true_end(c-1)
//   carry[b,c,:] = true_end(c-1); carry[b,0,:] = 0
// ---------------------------------------------------------------------------
__global__ void carry_kernel()
{
    const int b  = blockIdx.x;
    const int d4 = threadIdx.x;

    const float4* __restrict__ sm = reinterpret_cast<const float4*>(g_smoothed);
    float4* __restrict__ carry    = reinterpret_cast<float4*>(g_carry);

    float4 t_end = __ldg(sm + ((size_t)(b * J_ + CH_ - 1)) * D4_ + d4);
    carry[((size_t)(b * C_)) * D4_ + d4] = make_float4(0.f, 0.f, 0.f, 0.f);

    #pragma unroll 8
    for (int c = 1; c < C_; ++c) {
        carry[((size_t)(b * C_ + c)) * D4_ + d4] = t_end;
        const int je = c * CH_ + CH_ - 1;
        const float  A  = __ldg(g_aprefix + b * J_ + je);
        const float4 le = __ldg(sm + ((size_t)(b * J_ + je)) * D4_ + d4);
        t_end.x = fmaf(A, t_end.x, le.x);
        t_end.y = fmaf(A, t_end.y, le.y);
        t_end.z = fmaf(A, t_end.z, le.z);
        t_end.w = fmaf(A, t_end.w, le.w);
    }
}

// ---------------------------------------------------------------------------
// Kernel 3: gather + carry fixup, warp-per-row (64 B per thread).
//   out[b,l,:] = local[b,j,:] + Aprefix[b,j] * carry[b, j/CH_, :],  j = idx[b,l]
// grid = B_*L_/8 = 8192, block = 256 (8 warps).
// ---------------------------------------------------------------------------
__global__ void gather_kernel(float4* __restrict__ out)
{
    const int w    = (blockIdx.x * 256 + threadIdx.x) >> 5;  // global warp = b*L_+l
    const int lane = threadIdx.x & 31;
    const int b    = w >> 12;                                 // / L_

    const int   j  = __ldg(g_idx + w);
    const float ap = __ldg(g_aprefix + b * J_ + j);

    const float4* __restrict__ lo =
        reinterpret_cast<const float4*>(g_smoothed) + ((size_t)(b * J_ + j)) * D4_ + lane;
    const float4* __restrict__ cr =
        reinterpret_cast<const float4*>(g_carry) + ((size_t)(b * C_ + (j >> 4))) * D4_ + lane;
    float4* __restrict__ o = out + (size_t)w * D4_ + lane;

    #pragma unroll
    for (int k = 0; k < 4; ++k) {
        const float4 l4 = __ldg(lo + k * 32);
        const float4 c4 = __ldg(cr + k * 32);
        float4 r;
        r.x = fmaf(ap, c4.x, l4.x);
        r.y = fmaf(ap, c4.y, l4.y);
        r.z = fmaf(ap, c4.z, l4.z);
        r.w = fmaf(ap, c4.w, l4.w);
        __stcs(o + k * 32, r);
    }
}

// ---------------------------------------------------------------------------
extern "C" void kernel_launch(void* const* d_in, const int* in_sizes, int n_in,
                              void* d_out, int out_size)
{
    const float* emb   = (const float*)d_in[0];   // (B,J,D) f32
    const float* conf  = (const float*)d_in[1];   // (B,J)   f32
    const int*   umask = (const int*)d_in[2];     // (B,J)   bool->int32
    const int*   bmask = (const int*)d_in[3];     // (B,L)   bool->int32
    float4* out = (float4*)d_out;                 // (B,L,D) f32

    (void)in_sizes; (void)n_in; (void)out_size;

    ema_local_kernel<<<dim3(C_ + 1, B_), D4_>>>(emb, conf, umask, bmask);
    carry_kernel<<<B_, D4_>>>();
    gather_kernel<<<(B_ * L_) / 8, 256>>>(out);
}